// round 6
// baseline (speedup 1.0000x reference)
#include <cuda_runtime.h>
#include <math.h>

// Problem geometry (fixed by setup_inputs): B=16, C=3, H=W=512
#define NIMG   48
#define HDIM   512
#define WDIM   512
#define LIMG   (HDIM*WDIM)        // 262144 per image
#define NELEM  (NIMG*LIMG)        // 12,582,912
#define WPI    8192               // 32-bit mask words per image
#define NWORDS (NIMG*WPI)         // 393,216
#define WCPI   1024               // 256-element warp-chunks per image
#define NWC    (NIMG*WCPI)        // 49152
#define LOSS_BLOCKS  (NELEM/2048) // 6144
#define PLOSS_BLOCKS (NELEM/2048) // 6144

// ---- static scratch ----
__device__ float    gP[NELEM];    // compacted x at (t>0), per image, original order
__device__ float    gF[NELEM];    // compacted x at chosen mask, per image
__device__ unsigned gTB[NWORDS];  // packed bits: t > 0
__device__ unsigned gXB[NWORDS];  // packed bits: x > 0
__device__ unsigned gDL[NWORDS];  // 7x7-dilated bits (== aug_pos)
__device__ int gWOffPos[NWC], gWOffFp[NWC], gWOffNeg[NWC];
__device__ int gRowPos[NIMG], gRowFp[NIMG], gRowNeg[NIMG];
__device__ double gAcc;

__device__ __forceinline__ int reflect512(int c) {
    c = (c < 0) ? -c : c;
    return (c > 511) ? (1022 - c) : c;
}

__device__ __forceinline__ float softplusf(float z) {
    return fmaxf(z, 0.f) + __logf(1.f + __expf(-fabsf(z)));
}

__device__ __forceinline__ unsigned mask16_of(const float4 a, const float4 b,
                                              const float4 c, const float4 d) {
    unsigned m = 0;
    m |= (a.x > 0.f) ? 0x0001u : 0u;  m |= (a.y > 0.f) ? 0x0002u : 0u;
    m |= (a.z > 0.f) ? 0x0004u : 0u;  m |= (a.w > 0.f) ? 0x0008u : 0u;
    m |= (b.x > 0.f) ? 0x0010u : 0u;  m |= (b.y > 0.f) ? 0x0020u : 0u;
    m |= (b.z > 0.f) ? 0x0040u : 0u;  m |= (b.w > 0.f) ? 0x0080u : 0u;
    m |= (c.x > 0.f) ? 0x0100u : 0u;  m |= (c.y > 0.f) ? 0x0200u : 0u;
    m |= (c.z > 0.f) ? 0x0400u : 0u;  m |= (c.w > 0.f) ? 0x0800u : 0u;
    m |= (d.x > 0.f) ? 0x1000u : 0u;  m |= (d.y > 0.f) ? 0x2000u : 0u;
    m |= (d.z > 0.f) ? 0x4000u : 0u;  m |= (d.w > 0.f) ? 0x8000u : 0u;
    return m;
}

// ---- K1: bit pack (t>0), (x>0) via float4 loads + lane-pair shfl merge ----
__global__ void k_pack(const float* __restrict__ t, const float* __restrict__ x) {
    if (blockIdx.x == 0 && threadIdx.x == 0) gAcc = 0.0;
    int gtid = blockIdx.x * 256 + threadIdx.x;
    size_t base = (size_t)gtid * 16;
    const float4* tp = (const float4*)(t + base);
    const float4* xp = (const float4*)(x + base);
    float4 t0 = tp[0], t1 = tp[1], t2 = tp[2], t3 = tp[3];
    float4 x0 = xp[0], x1 = xp[1], x2 = xp[2], x3 = xp[3];
    unsigned mt = mask16_of(t0, t1, t2, t3);
    unsigned mx = mask16_of(x0, x1, x2, x3);
    unsigned ot = __shfl_xor_sync(0xFFFFFFFFu, mt, 1);
    unsigned ox = __shfl_xor_sync(0xFFFFFFFFu, mx, 1);
    if (!(gtid & 1)) {
        int w = gtid >> 1;
        gTB[w] = mt | (ot << 16);
        gXB[w] = mx | (ox << 16);
    }
}

// ---- K2: fused 7-wide horizontal + vertical OR-dilation (reflect) ----
__device__ __forceinline__ unsigned hdil(const unsigned* __restrict__ rowTB, int ww) {
    unsigned cur = rowTB[ww];
    unsigned long long ext = ((unsigned long long)cur) << 3;  // bit k <-> col c0-3+k
    if (ww > 0) {
        ext |= (rowTB[ww - 1] >> 29);
    } else {  // reflect: cols -1,-2,-3 -> 1,2,3
        ext |= ((cur >> 3) & 1u) | (((cur >> 2) & 1u) << 1) | (((cur >> 1) & 1u) << 2);
    }
    if (ww < 15) {
        ext |= ((unsigned long long)(rowTB[ww + 1] & 7u)) << 35;
    } else {  // reflect: cols 512,513,514 -> 510,509,508
        ext |= ((unsigned long long)((cur >> 30) & 1u)) << 35
             | ((unsigned long long)((cur >> 29) & 1u)) << 36
             | ((unsigned long long)((cur >> 28) & 1u)) << 37;
    }
    unsigned long long m = ext;
    m |= m >> 1; m |= m >> 2; m |= m >> 3;   // OR over 7-window
    return (unsigned)m;
}

__global__ void k_dil() {
    int w = blockIdx.x * blockDim.x + threadIdx.x;
    int img = w >> 13, rem = w & 8191, h = rem >> 4, ww = rem & 15;
    const unsigned* ib = gTB + (img << 13);
    unsigned d = 0u;
    #pragma unroll
    for (int dh = -3; dh <= 3; dh++) {
        int hh = reflect512(h + dh);
        d |= hdil(ib + (hh << 4), ww);
    }
    gDL[w] = d;
}

// ---- K3: per-image counts + scan -> per-warpchunk (256-elem) offsets ----
__global__ void k_countscan() {
    int img = blockIdx.x, tid = threadIdx.x;
    const unsigned* tb = gTB + (img << 13);
    const unsigned* xb = gXB + (img << 13);
    const unsigned* db = gDL + (img << 13);
    int w0 = tid * 32;                 // 4 warpchunks (8 words each) per thread
    int lp[4], lf[4], ln[4];
    int p = 0, f = 0, n = 0;
    #pragma unroll
    for (int j = 0; j < 4; j++) {
        int pj = 0, fj = 0, nj = 0;
        #pragma unroll
        for (int k = 0; k < 8; k++) {
            unsigned T = tb[w0 + j * 8 + k], X = xb[w0 + j * 8 + k], D = db[w0 + j * 8 + k];
            pj += __popc(T);
            fj += __popc(X & ~D);
            nj += __popc(~D);
        }
        lp[j] = p; lf[j] = f; ln[j] = n;   // thread-local exclusive
        p += pj; f += fj; n += nj;
    }
    int lane = tid & 31, w = tid >> 5;
    int ip = p, iff = f, in = n;
    #pragma unroll
    for (int o = 1; o < 32; o <<= 1) {
        int ap = __shfl_up_sync(0xFFFFFFFFu, ip, o);
        int af = __shfl_up_sync(0xFFFFFFFFu, iff, o);
        int an = __shfl_up_sync(0xFFFFFFFFu, in, o);
        if (lane >= o) { ip += ap; iff += af; in += an; }
    }
    __shared__ int wp[8], wf[8], wn[8];
    if (lane == 31) { wp[w] = ip; wf[w] = iff; wn[w] = in; }
    __syncthreads();
    int bp = 0, bf = 0, bn = 0;
    for (int k = 0; k < w; k++) { bp += wp[k]; bf += wf[k]; bn += wn[k]; }
    int ep = bp + ip - p, ef = bf + iff - f, en = bn + in - n;  // thread exclusive
    int base = img * LIMG;
    int wc0 = img * WCPI + tid * 4;
    #pragma unroll
    for (int j = 0; j < 4; j++) {
        gWOffPos[wc0 + j] = base + ep + lp[j];
        gWOffFp[wc0 + j]  = base + ef + lf[j];
        gWOffNeg[wc0 + j] = base + en + ln[j];
    }
    if (tid == 255) { gRowPos[img] = bp + ip; gRowFp[img] = bf + iff; gRowNeg[img] = bn + in; }
}

// ---- K4: warp-autonomous compaction, 8 elems/thread, independent stores ----
__global__ void k_write(const float* __restrict__ x) {
    int wc   = (blockIdx.x * blockDim.x + threadIdx.x) >> 5;  // global 256-elem chunk
    int lane = threadIdx.x & 31;
    int img  = wc >> 10;
    bool useFp = gRowFp[img] > 0;
    int ebase = wc * 256 + lane * 8;
    unsigned wordT = gTB[(wc << 3) + (lane >> 2)];
    unsigned wordD = gDL[(wc << 3) + (lane >> 2)];
    int sh = (lane & 3) << 3;
    unsigned tb = (wordT >> sh) & 0xFFu;
    unsigned db = (wordD >> sh) & 0xFFu;

    const float4* xp = (const float4*)(x + ebase);
    float4 v0 = xp[0], v1 = xp[1];
    float xv[8] = {v0.x, v0.y, v0.z, v0.w, v1.x, v1.y, v1.z, v1.w};
    unsigned sb = 0u;
    #pragma unroll
    for (int i = 0; i < 8; i++) if (xv[i] > 0.f) sb |= 1u << i;
    unsigned cm = (useFp ? (sb & ~db) : ~db) & 0xFFu;

    int packed = __popc(tb) | (__popc(cm) << 16);
    int s = packed;
    #pragma unroll
    for (int o = 1; o < 32; o <<= 1) {
        int nn = __shfl_up_sync(0xFFFFFFFFu, s, o);
        if (lane >= o) s += nn;
    }
    int excl = s - packed;

    // Positives: independent predicated stores (dst via popc prefix)
    {
        int base0 = gWOffPos[wc] + (excl & 0xFFFF);
        #pragma unroll
        for (int i = 0; i < 8; i++) {
            if ((tb >> i) & 1) gP[base0 + __popc(tb & ((1u << i) - 1u))] = xv[i];
        }
    }
    // Chosen-mask values: skipped entirely when warp has none (common case)
    if (__any_sync(0xFFFFFFFFu, cm)) {
        int base1 = (useFp ? gWOffFp[wc] : gWOffNeg[wc]) + (excl >> 16);
        #pragma unroll
        for (int i = 0; i < 8; i++) {
            if ((cm >> i) & 1) gF[base1 + __popc(cm & ((1u << i) - 1u))] = xv[i];
        }
    }
}

// ---- K5: fused loss with batched logs.
//      Blocks [0,LOSS_BLOCKS): per-element terms paired with x.
//      Blocks [LOSS_BLOCKS,+PLOSS_BLOCKS): P-only terms with cyclic multiplicity. ----
__global__ void k_loss(const float* __restrict__ x) {
    int b = blockIdx.x;
    float acc = 0.f;
    if (b < LOSS_BLOCKS) {
        int img = b >> 7;
        int e0  = (b & 127) * 2048 + threadIdx.x;      // within-image index
        unsigned cp = (unsigned)gRowPos[img];
        unsigned rf = (unsigned)gRowFp[img];
        unsigned rn = (unsigned)gRowNeg[img];
        unsigned cf = rf ? rf : rn;
        const float* __restrict__ Pb = gP + (size_t)img * LIMG;
        const float* __restrict__ Fb = gF + (size_t)img * LIMG;
        const float* __restrict__ xb = x + (size_t)img * LIMG;
        const unsigned* __restrict__ tbw = gTB + ((size_t)img * LIMG >> 5);
        unsigned rP = cp ? ((unsigned)e0 % cp) : 0u;
        unsigned rF = cf ? ((unsigned)e0 % cf) : 0u;
        float lin = 0.f, prod = 1.f;
        #pragma unroll
        for (int j = 0; j < 8; j++) {
            int e = e0 + 256 * j;
            float xx = xb[e];
            unsigned tbit = (tbw[e >> 5] >> (e & 31)) & 1u;
            float p = cp ? Pb[rP] : 5.0f;
            float s = p * xx;
            lin += fmaxf(s, 0.f) - (tbit ? s : 0.f);
            prod *= 1.f + __expf(-fabsf(s));
            if (cf) {
                float f = Fb[rF];
                lin += 0.1f * softplusf(p * f);
                rF += 256u; while (rF >= cf) rF -= cf;
            }
            if (cp) { rP += 256u; while (rP >= cp) rP -= cp; }
        }
        acc = lin + __logf(prod);
    } else {
        int pb  = b - LOSS_BLOCKS;
        int img = pb >> 7;
        int i0  = (pb & 127) * 2048 + threadIdx.x;
        unsigned cp = (unsigned)gRowPos[img];
        unsigned rf = (unsigned)gRowFp[img];
        unsigned rn = (unsigned)gRowNeg[img];
        bool cf0 = (rf == 0u && rn == 0u);             // F is the -5 fallback
        if (cp) {
            unsigned q = (unsigned)LIMG / cp, rr = (unsigned)LIMG - q * cp;
            const float* __restrict__ Pb = gP + (size_t)img * LIMG;
            if (q <= 6u) {
                float lin = 0.f, prodA = 1.f, prodB = 1.f;
                #pragma unroll
                for (int j = 0; j < 8; j++) {
                    unsigned i = (unsigned)i0 + 256u * j;
                    if (i < cp) {
                        float pv = Pb[i];
                        unsigned mi = q + (i < rr ? 1u : 0u);
                        float fm = (float)mi;
                        float e1 = 1.f + __expf(-fabsf(pv));
                        lin += fm * fmaxf(-pv, 0.f);
                        float pa = 1.f;
                        for (unsigned k = 0; k < mi; k++) pa *= e1;
                        prodA *= pa;
                        if (cf0) {
                            float e5 = 1.f + __expf(-fabsf(5.f * pv));
                            lin += 0.1f * fm * fmaxf(-5.f * pv, 0.f);
                            float pb2 = 1.f;
                            for (unsigned k = 0; k < mi; k++) pb2 *= e5;
                            prodB *= pb2;
                        }
                    }
                }
                acc = lin + __logf(prodA) + (cf0 ? 0.1f * __logf(prodB) : 0.f);
            } else {
                #pragma unroll
                for (int j = 0; j < 8; j++) {
                    unsigned i = (unsigned)i0 + 256u * j;
                    if (i < cp) {
                        float pv = Pb[i];
                        float m = (float)(q + (i < rr ? 1u : 0u));
                        float term = softplusf(-pv);
                        if (cf0) term += 0.1f * softplusf(-5.0f * pv);
                        acc += m * term;
                    }
                }
            }
        } else if ((pb & 127) == 0 && threadIdx.x == 0) {
            // no positives: p == 5 everywhere
            float t2 = softplusf(-5.f);
            float t3 = cf0 ? 0.1f * softplusf(-25.f) : 0.f;
            acc = (float)LIMG * (t2 + t3);
        }
    }

    int lane = threadIdx.x & 31, wid = threadIdx.x >> 5;
    #pragma unroll
    for (int o = 16; o > 0; o >>= 1) acc += __shfl_down_sync(0xFFFFFFFFu, acc, o);
    __shared__ float ws[8];
    if (lane == 0) ws[wid] = acc;
    __syncthreads();
    if (threadIdx.x == 0) {
        float s = 0.f;
        #pragma unroll
        for (int k = 0; k < 8; k++) s += ws[k];
        atomicAdd(&gAcc, (double)s);
    }
}

// ---- K6: finalize ----
__global__ void k_final(float* __restrict__ out) {
    out[0] = (float)(gAcc / (double)NELEM);
}

extern "C" void kernel_launch(void* const* d_in, const int* in_sizes, int n_in,
                              void* d_out, int out_size) {
    const float* x = (const float*)d_in[0];   // input
    const float* t = (const float*)d_in[1];   // target
    float* out = (float*)d_out;
    (void)in_sizes; (void)n_in; (void)out_size;

    k_pack     <<<NELEM / 4096, 256>>>(t, x);
    k_dil      <<<NWORDS / 256, 256>>>();
    k_countscan<<<NIMG, 256>>>();
    k_write    <<<(NWC * 32) / 512, 512>>>(x);
    k_loss     <<<LOSS_BLOCKS + PLOSS_BLOCKS, 256>>>(x);
    k_final    <<<1, 1>>>(out);
}